// round 14
// baseline (speedup 1.0000x reference)
#include <cuda_runtime.h>
#include <cuda_bf16.h>
#include <cstdint>

// ---------------- problem constants ----------------
constexpr int NB  = 2;
constexpr int NH  = 8;
constexpr int NC  = 2048;
constexpr int NE  = 1024;
constexpr int ND  = 64;
constexpr int NKP = 8;
constexpr int NP  = 16;
constexpr int BHC = NB * NH * NC;          // 32768
constexpr int HD  = NH * ND;               // 512
constexpr int M   = NB * NC;               // 4096
constexpr int NQKV = 3 * HD;               // 1536

// ---------------- scratch (__device__ globals; no allocation allowed) ----------------
__device__ float g_Q[NB * NH * NC * ND];
__device__ float g_K[NB * NH * NC * ND];
__device__ float g_V[NB * NH * NC * ND];
__device__ int   g_idx[BHC * NP];
__device__ float g_dens[(size_t)BHC * 128];
__device__ float g_part[NB * NH * 16 * 128];       // phase-1 partial sums
__device__ float g_Sinv[NB * NH * 128];
__device__ float g_w[BHC * NP];
__device__ float g_nw[BHC * NP];

// bf16 split operands
__device__ __nv_bfloat16 g_xh[(size_t)M * NE];
__device__ __nv_bfloat16 g_xl[(size_t)M * NE];
__device__ __nv_bfloat16 g_Wqkvh[(size_t)NQKV * NE];   // [n, k] K-major, scale folded
__device__ __nv_bfloat16 g_Wqkvl[(size_t)NQKV * NE];
__device__ __nv_bfloat16 g_Wuh[(size_t)NE * HD];       // [n=1024, k=512]
__device__ __nv_bfloat16 g_Wul[(size_t)NE * HD];
__device__ __nv_bfloat16 g_uh[(size_t)M * HD];
__device__ __nv_bfloat16 g_ul[(size_t)M * HD];

// ---------------- PTX helpers ----------------
__device__ __forceinline__ uint32_t smem_u32(const void* p) {
    uint32_t a;
    asm("{ .reg .u64 t; cvta.to.shared.u64 t, %1; cvt.u32.u64 %0, t; }" : "=r"(a) : "l"(p));
    return a;
}

__device__ __forceinline__ void cp_async16(uint32_t dst, const void* src) {
    asm volatile("cp.async.cg.shared.global [%0], [%1], 16;" :: "r"(dst), "l"(src) : "memory");
}

__device__ __forceinline__ void ldsm_x4(uint32_t* r, uint32_t addr) {
    asm volatile("ldmatrix.sync.aligned.m8n8.x4.shared.b16 {%0,%1,%2,%3}, [%4];"
                 : "=r"(r[0]), "=r"(r[1]), "=r"(r[2]), "=r"(r[3]) : "r"(addr));
}

__device__ __forceinline__ void mma16816(float* c, const uint32_t* a,
                                         uint32_t b0, uint32_t b1) {
    asm volatile(
        "mma.sync.aligned.m16n8k16.row.col.f32.bf16.bf16.f32 "
        "{%0,%1,%2,%3}, {%4,%5,%6,%7}, {%8,%9}, {%0,%1,%2,%3};"
        : "+f"(c[0]), "+f"(c[1]), "+f"(c[2]), "+f"(c[3])
        : "r"(a[0]), "r"(a[1]), "r"(a[2]), "r"(a[3]), "r"(b0), "r"(b1));
}

__device__ __forceinline__ void stwt4(float* p, float4 v) {
    asm volatile("st.global.wt.v4.f32 [%0], {%1,%2,%3,%4};"
                 :: "l"(p), "f"(v.x), "f"(v.y), "f"(v.z), "f"(v.w) : "memory");
}

// ---------------- conversion kernels ----------------
__global__ __launch_bounds__(256) void conv_x(const float* __restrict__ in)
{
    const int i = blockIdx.x * blockDim.x + threadIdx.x;      // pairs
    float2 v = ((const float2*)in)[i];
    __nv_bfloat16 h0 = __float2bfloat16(v.x), h1 = __float2bfloat16(v.y);
    __nv_bfloat162 hv; hv.x = h0; hv.y = h1;
    __nv_bfloat162 lv;
    lv.x = __float2bfloat16(v.x - __bfloat162float(h0));
    lv.y = __float2bfloat16(v.y - __bfloat162float(h1));
    ((__nv_bfloat162*)g_xh)[i] = hv;
    ((__nv_bfloat162*)g_xl)[i] = lv;
}

// fused coalesced transpose of all 4 weight matrices: W[k,n] -> Wt[n,k] hi/lo bf16
__global__ __launch_bounds__(256) void conv_w(const float* __restrict__ Wq,
                                              const float* __restrict__ Wk,
                                              const float* __restrict__ Wv,
                                              const float* __restrict__ Wu)
{
    __shared__ float sm[32][33];
    const int bid = blockIdx.x;
    const int mat = bid >> 9;          // 512 tiles per matrix
    const int t   = bid & 511;

    const float* src;
    __nv_bfloat16 *oh, *ol;
    int cols_in, Kd;
    float scale;
    if (mat == 0)      { src = Wq; oh = g_Wqkvh;                       ol = g_Wqkvl;                       cols_in = 512;  Kd = 1024; scale = 0.125f; }
    else if (mat == 1) { src = Wk; oh = g_Wqkvh + (size_t)HD * NE;     ol = g_Wqkvl + (size_t)HD * NE;     cols_in = 512;  Kd = 1024; scale = 0.125f; }
    else if (mat == 2) { src = Wv; oh = g_Wqkvh + (size_t)2 * HD * NE; ol = g_Wqkvl + (size_t)2 * HD * NE; cols_in = 512;  Kd = 1024; scale = 1.0f;   }
    else               { src = Wu; oh = g_Wuh;                         ol = g_Wul;                         cols_in = 1024; Kd = 512;  scale = 1.0f;   }

    int tn, tk;
    if (mat < 3) { tn = t & 15; tk = t >> 4; }
    else         { tn = t & 31; tk = t >> 5; }
    const int k0 = tk * 32, n0 = tn * 32;

    const int c = threadIdx.x & 31;
    const int r = threadIdx.x >> 5;
#pragma unroll
    for (int rr = 0; rr < 4; rr++) {
        const int row = r + rr * 8;
        sm[row][c] = src[(size_t)(k0 + row) * cols_in + n0 + c];
    }
    __syncthreads();
#pragma unroll
    for (int rr = 0; rr < 4; rr++) {
        const int rp = r + rr * 8;
        const int n = n0 + rp;
        const int k = k0 + c;
        float v = sm[c][rp] * scale;
        __nv_bfloat16 h = __float2bfloat16(v);
        oh[(size_t)n * Kd + k] = h;
        ol[(size_t)n * Kd + k] = __float2bfloat16(v - __bfloat162float(h));
    }
}

// ---------------- HMMA bf16-split GEMM (4 stages, wait 2; proven config) ----------------
// MODE 0: C = x @ [Wq*s | Wk*s | Wv]  (K=1024, N=1536) -> g_Q/g_K/g_V (b,h,c,d)
//         + trailing filler blocks zero-fill 'outp' (the attentions buffer)
// MODE 1: C = united @ Wu + bu        (K=512,  N=1024) -> outp row-major
constexpr int BM = 128, BN = 128, BK = 16;
constexpr int ROWB  = 48;                    // padded row stride (bytes) for 32B of data
constexpr int MAT_B = 128 * ROWB;            // 6144 bytes per matrix tile
constexpr int STG_B = 4 * MAT_B;             // Ah, Al, Bh, Bl  = 24576
constexpr int NSTG  = 4;
constexpr int SMEM_GEMM = NSTG * STG_B;      // 98304

constexpr int G0_TILES = (NQKV / BN) * (M / BM);   // 384
constexpr int NFILL    = 256;                      // filler blocks appended to gemm0
constexpr size_t ATT4  = (size_t)NB * NH * NC * NC / 4;  // 16M float4

template <int MODE>
__global__ __launch_bounds__(256, 2)
void gemm_mma(const float* __restrict__ bias, float* __restrict__ outp)
{
    constexpr int K   = (MODE == 0) ? NE : HD;
    constexpr int NCH = K / BK;

    int bx, by;
    if (MODE == 0) {
        const int bid = blockIdx.x;
        if (bid >= G0_TILES) {
            // filler: streaming zero-fill of attentions (write-through, no L2 pollution)
            const int f = bid - G0_TILES;
            float4* dst = (float4*)outp;
            const float4 z = make_float4(0.f, 0.f, 0.f, 0.f);
            for (size_t i = (size_t)f * 256 + threadIdx.x; i < ATT4;
                 i += (size_t)NFILL * 256)
                stwt4((float*)(dst + i), z);
            return;
        }
        bx = bid % (NQKV / BN);
        by = bid / (NQKV / BN);
    } else {
        bx = blockIdx.x;
        by = blockIdx.y;
    }

    extern __shared__ char sm[];
    const uint32_t sb = smem_u32(sm);

    const int tid  = threadIdx.x;
    const int wid  = tid >> 5;
    const int lane = tid & 31;
    const int warp_m = wid & 1;        // 0..1 -> 64-row slice
    const int warp_n = wid >> 1;       // 0..3 -> 32-col slice
    const int row0 = by * BM;
    const int col0 = bx * BN;

    const __nv_bfloat16* __restrict__ Ah = (MODE == 0) ? g_xh : g_uh;
    const __nv_bfloat16* __restrict__ Al = (MODE == 0) ? g_xl : g_ul;
    const __nv_bfloat16* __restrict__ Bh = (MODE == 0) ? g_Wqkvh : g_Wuh;
    const __nv_bfloat16* __restrict__ Bl = (MODE == 0) ? g_Wqkvl : g_Wul;

    // per-thread cp.async mapping: 1024 16B chunks (4 mats x 128 rows x 2)
    const char* gsrc[4];
    uint32_t    sdst[4];
#pragma unroll
    for (int i = 0; i < 4; i++) {
        const int u   = tid + i * 256;
        const int mat = u >> 8;
        const int r   = (u >> 1) & 127;
        const int c   = u & 1;
        const __nv_bfloat16* base = (mat == 0) ? Ah : (mat == 1) ? Al
                                  : (mat == 2) ? Bh : Bl;
        const int rb = (mat < 2) ? row0 : col0;
        gsrc[i] = (const char*)(base + (size_t)(rb + r) * K) + c * 16;
        sdst[i] = sb + mat * MAT_B + r * ROWB + c * 16;
    }

    float acc[4][4][4];
#pragma unroll
    for (int a = 0; a < 4; a++)
#pragma unroll
        for (int b = 0; b < 4; b++)
#pragma unroll
            for (int d = 0; d < 4; d++) acc[a][b][d] = 0.f;

    // ldmatrix base addresses (within stage 0)
    const uint32_t a_addr = sb + (warp_m * 64 + (lane & 15)) * ROWB + ((lane >> 4) & 1) * 16;
    const uint32_t b_addr = sb + 2 * MAT_B +
        (warp_n * 32 + (lane & 7) + ((lane & 16) ? 8 : 0)) * ROWB + ((lane & 8) ? 16 : 0);

    // prologue: stages 0..2
#pragma unroll
    for (int s = 0; s < 3; s++) {
#pragma unroll
        for (int i = 0; i < 4; i++)
            cp_async16(sdst[i] + s * STG_B, gsrc[i] + (size_t)s * 32);
        asm volatile("cp.async.commit_group;" ::: "memory");
    }

    for (int kb = 0; kb < NCH; kb++) {
        asm volatile("cp.async.wait_group 2;" ::: "memory");
        __syncthreads();

        const uint32_t so = (kb & (NSTG - 1)) * STG_B;
        uint32_t ah[4][4], al[4][4], bh[2][4], bl[2][4];
#pragma unroll
        for (int mf = 0; mf < 4; mf++) ldsm_x4(ah[mf], a_addr + so + mf * 16 * ROWB);
#pragma unroll
        for (int mf = 0; mf < 4; mf++) ldsm_x4(al[mf], a_addr + so + MAT_B + mf * 16 * ROWB);
#pragma unroll
        for (int gp = 0; gp < 2; gp++) ldsm_x4(bh[gp], b_addr + so + gp * 16 * ROWB);
#pragma unroll
        for (int gp = 0; gp < 2; gp++) ldsm_x4(bl[gp], b_addr + so + MAT_B + gp * 16 * ROWB);

        // term-outer: 16 independent accumulator chains per term
#pragma unroll
        for (int term = 0; term < 3; term++) {
#pragma unroll
            for (int mf = 0; mf < 4; mf++)
#pragma unroll
                for (int nf = 0; nf < 4; nf++) {
                    const uint32_t* af = (term == 2) ? al[mf] : ah[mf];
                    const uint32_t b0 = (term == 1) ? bl[nf >> 1][(nf & 1) * 2]
                                                    : bh[nf >> 1][(nf & 1) * 2];
                    const uint32_t b1 = (term == 1) ? bl[nf >> 1][(nf & 1) * 2 + 1]
                                                    : bh[nf >> 1][(nf & 1) * 2 + 1];
                    mma16816(acc[mf][nf], af, b0, b1);
                }
        }

        if (kb + 3 < NCH) {
            const uint32_t sn = ((kb + 3) & (NSTG - 1)) * STG_B;
#pragma unroll
            for (int i = 0; i < 4; i++)
                cp_async16(sdst[i] + sn, gsrc[i] + (size_t)(kb + 3) * 32);
            asm volatile("cp.async.commit_group;" ::: "memory");
        }
    }

    // epilogue
    const int gid = lane >> 2;
    const int tig = lane & 3;
#pragma unroll
    for (int mf = 0; mf < 4; mf++) {
#pragma unroll
        for (int nf = 0; nf < 4; nf++) {
            const int mrow = row0 + warp_m * 64 + mf * 16 + gid;
            const int ncol = col0 + warp_n * 32 + nf * 8 + tig * 2;
            if (MODE == 0) {
                const int mat = ncol >> 9;
                const int hd0 = ncol & 511;
                float* base = (mat == 0) ? g_Q : (mat == 1) ? g_K : g_V;
                const int h = hd0 >> 6, d = hd0 & 63;
#pragma unroll
                for (int half = 0; half < 2; half++) {
                    const int m = mrow + half * 8;
                    const size_t off =
                        ((size_t)(((m >> 11) * NH + h) * NC + (m & (NC - 1)))) * ND + d;
                    *(float2*)(base + off) =
                        make_float2(acc[mf][nf][half * 2], acc[mf][nf][half * 2 + 1]);
                }
            } else {
                const float2 bb = *(const float2*)(bias + ncol);
#pragma unroll
                for (int half = 0; half < 2; half++) {
                    const int m = mrow + half * 8;
                    *(float2*)(outp + (size_t)m * NE + ncol) =
                        make_float2(acc[mf][nf][half * 2] + bb.x,
                                    acc[mf][nf][half * 2 + 1] + bb.y);
                }
            }
        }
    }
}

// ---------------- idx + per-point densities (warp per (b,h,c), lane-parallel) ----------------
__global__ __launch_bounds__(256)
void dens_k(const float* __restrict__ means, const float* __restrict__ sigmas)
{
    const unsigned FULL = 0xffffffffu;
    const int gw   = (blockIdx.x * blockDim.x + threadIdx.x) >> 5;
    const int lane = threadIdx.x & 31;
    if (gw >= BHC) return;

    float mk = 0.f, sk = 1.f;
    if (lane < NKP) {
        mk = means[(size_t)gw * NKP + lane];
        sk = sigmas[(size_t)gw * NKP + lane];
    }

    // lanes 0..15 each own one point p = pl (mirrored on 16..31)
    const int pl = lane & 15;
    const float mp = __shfl_sync(FULL, mk, pl >> 1);
    int i0 = min(NC - 1, max(0, (int)floorf(mp)));
    const int myidx = (pl & 1) ? min(NC - 1, i0 + 1) : i0;

    // dup detection: any earlier point with same index
    const unsigned peers = __match_any_sync(FULL, myidx);
    const int mydup = ((peers & 0xFFFFu & ((1u << pl) - 1u)) != 0) ? 1 : 0;

    if (lane < NP) g_idx[gw * NP + lane] = myidx;

    // density: lane covers pk = lane*4 .. lane*4+3  ->  p = lane>>1, k = (lane&1)*4 + u
    const int   ip  = __shfl_sync(FULL, myidx, lane >> 1);
    const int   dp_ = __shfl_sync(FULL, mydup, lane >> 1);
    const float fi  = (float)ip;
    const int kb4 = (lane & 1) * 4;
    float dv[4];
#pragma unroll
    for (int u = 0; u < 4; u++) {
        const float mku = __shfl_sync(FULL, mk, kb4 + u);
        const float sku = __shfl_sync(FULL, sk, kb4 + u);
        const float t = (fi - mku) / sku;
        dv[u] = dp_ ? 0.f : __expf(-0.5f * t * t);
    }
    *(float4*)&g_dens[(size_t)gw * 128 + lane * 4] =
        make_float4(dv[0], dv[1], dv[2], dv[3]);
}

// ---------------- reduce densities over c: phase 1 (256 blocks) ----------------
__global__ __launch_bounds__(256)
void sum1_k()
{
    const int bh    = blockIdx.x >> 4;
    const int slice = blockIdx.x & 15;       // 128 c's per slice
    const int tid   = threadIdx.x;
    const int pk    = tid & 127;
    const int half  = tid >> 7;
    float acc = 0.f;
    const float* dp = g_dens + ((size_t)bh * NC + slice * 128) * 128 + pk;
    for (int c = half; c < 128; c += 2) acc += dp[(size_t)c * 128];
    __shared__ float sh[256];
    sh[tid] = acc;
    __syncthreads();
    if (tid < 128)
        g_part[blockIdx.x * 128 + tid] = sh[tid] + sh[tid + 128];
}

// ---------------- phase 2: fold 16 partials, invert ----------------
__global__ __launch_bounds__(128)
void sum2_k()
{
    const int bh  = blockIdx.x;
    const int tid = threadIdx.x;
    float acc = 0.f;
#pragma unroll
    for (int s = 0; s < 16; s++)
        acc += g_part[(bh * 16 + s) * 128 + tid];
    g_Sinv[bh * 128 + tid] = 1.0f / (acc + 1e-8f);
}

// ---------------- density-weighted values -> per-point weights ----------------
__global__ __launch_bounds__(256)
void wgt_k(const float* __restrict__ values)
{
    const int gid  = blockIdx.x * blockDim.x + threadIdx.x;
    const int base = gid >> 4;
    const int p    = gid & 15;
    const int bh   = base >> 11;
    const float* vv = values + (size_t)base * NKP;
    const float* dd = g_dens + (size_t)base * 128 + p * 8;
    const float* si = g_Sinv + bh * 128 + p * 8;
    float w = 0.f;
#pragma unroll
    for (int k = 0; k < NKP; k++) w += vv[k] * dd[k] * si[k];
    g_w[gid] = w;
}

// ---------------- attention core (warp per (b,h,c)) ----------------
// epilogue writes the bf16 hi/lo split of 'united' directly (fused conv_u)
__global__ __launch_bounds__(256)
void attn_k()
{
    const unsigned FULL = 0xffffffffu;
    const int gw   = (blockIdx.x * blockDim.x + threadIdx.x) >> 5;
    const int lane = threadIdx.x & 31;
    if (gw >= BHC) return;
    const int bh = gw >> 11;

    const float2* Q2 = (const float2*)g_Q;
    const float2* K2 = (const float2*)g_K + (size_t)bh * NC * 32;
    const float2* V2 = (const float2*)g_V + (size_t)bh * NC * 32;

    const float2 q = Q2[(size_t)gw * 32 + lane];

    int   myidx = 0;
    float myw   = 0.f;
    if (lane < NP) {
        myidx = g_idx[gw * NP + lane];
        myw   = g_w[gw * NP + lane];
    }

    float dot[NP];
#pragma unroll
    for (int p = 0; p < NP; p++) {
        const int ip = __shfl_sync(FULL, myidx, p);
        const float2 kv = K2[(size_t)ip * 32 + lane];
        float pa = q.x * kv.x + q.y * kv.y;
#pragma unroll
        for (int o = 16; o > 0; o >>= 1) pa += __shfl_xor_sync(FULL, pa, o);
        dot[p] = pa;
    }

    float lg[NP], mx = -3.0e38f;
#pragma unroll
    for (int p = 0; p < NP; p++) {
        const float wp = __shfl_sync(FULL, myw, p);
        lg[p] = wp * dot[p];
        mx = fmaxf(mx, lg[p]);
    }
    float ssum = 0.f;
#pragma unroll
    for (int p = 0; p < NP; p++) {
        lg[p] = expf(lg[p] - mx);
        ssum += lg[p];
    }
    const float inv = 1.0f / ssum;

    float2 acc = make_float2(0.f, 0.f);
#pragma unroll
    for (int p = 0; p < NP; p++) {
        const float nw = lg[p] * inv;
        lg[p] = nw;
        const int ip = __shfl_sync(FULL, myidx, p);
        const float2 vv = V2[(size_t)ip * 32 + lane];
        acc.x = fmaf(nw, vv.x, acc.x);
        acc.y = fmaf(nw, vv.y, acc.y);
    }

    const int b = gw >> 14;
    const int h = (gw >> 11) & (NH - 1);
    const int c = gw & (NC - 1);
    // bf16 hi/lo split of united, stored directly for GEMM1
    __nv_bfloat162 hv, lv;
    hv.x = __float2bfloat16(acc.x);
    hv.y = __float2bfloat16(acc.y);
    lv.x = __float2bfloat16(acc.x - __bfloat162float(hv.x));
    lv.y = __float2bfloat16(acc.y - __bfloat162float(hv.y));
    const size_t uoff = (size_t)(b * NC + c) * (HD / 2) + h * (ND / 2) + lane;
    ((__nv_bfloat162*)g_uh)[uoff] = hv;
    ((__nv_bfloat162*)g_ul)[uoff] = lv;

    if (lane < NP) g_nw[gw * NP + lane] = lg[lane];
}

// ---------------- sparse add into pre-zeroed attentions (warp per row) ----------------
__global__ __launch_bounds__(256)
void scat_add(float* __restrict__ att)
{
    const unsigned FULL = 0xffffffffu;
    const int gw   = (blockIdx.x * blockDim.x + threadIdx.x) >> 5;  // row (b,h,c)
    const int lane = threadIdx.x & 31;
    if (gw >= BHC) return;

    int   myidx = -1 - lane;     // unique sentinel for lanes >= NP
    float mynw  = 0.f;
    if (lane < NP) {
        myidx = g_idx[gw * NP + lane];
        mynw  = g_nw[gw * NP + lane];
    }

    // combine duplicate columns: uniform 16-shfl scan (no divergence)
    float s = 0.f;
    int leader = lane;
#pragma unroll
    for (int q = 0; q < NP; q++) {
        const int   iq = __shfl_sync(FULL, myidx, q);
        const float nq = __shfl_sync(FULL, mynw, q);
        if (iq == myidx) {
            s += nq;
            if (q < leader) leader = q;
        }
    }
    if (lane < NP && lane == leader)
        att[(size_t)gw * NC + myidx] = s;
}

// ---------------- launch ----------------
extern "C" void kernel_launch(void* const* d_in, const int* in_sizes, int n_in,
                              void* d_out, int out_size)
{
    const float* x      = (const float*)d_in[0];
    // d_in[1] = attention_mask (unused)
    const float* means  = (const float*)d_in[2];
    const float* sigmas = (const float*)d_in[3];
    const float* values = (const float*)d_in[4];
    const float* Wk     = (const float*)d_in[5];
    const float* Wq     = (const float*)d_in[6];
    const float* Wv     = (const float*)d_in[7];
    const float* Wu     = (const float*)d_in[8];
    const float* bu     = (const float*)d_in[9];

    float* out = (float*)d_out;
    float* att = out + (size_t)NB * NC * NE;

    // unconditional (deterministic, capture-safe): enable 96KB dynamic smem
    cudaFuncSetAttribute(gemm_mma<0>, cudaFuncAttributeMaxDynamicSharedMemorySize, SMEM_GEMM);
    cudaFuncSetAttribute(gemm_mma<1>, cudaFuncAttributeMaxDynamicSharedMemorySize, SMEM_GEMM);

    // operand conversion (coalesced)
    conv_x<<<(M * NE / 2) / 256, 256>>>(x);
    conv_w<<<2048, 256>>>(Wq, Wk, Wv, Wu);
    dens_k<<<BHC / 8, 256>>>(means, sigmas);   // 3rd: independent of convs

    // 4th launch -> profiled. GEMM tiles + trailing filler blocks zero the attentions buffer.
    gemm_mma<0><<<G0_TILES + NFILL, 256, SMEM_GEMM>>>(nullptr, att);

    sum1_k<<<NB * NH * 16, 256>>>();
    sum2_k<<<NB * NH, 128>>>();
    wgt_k<<<BHC * NP / 256, 256>>>(values);
    attn_k<<<BHC / 8, 256>>>();

    gemm_mma<1><<<dim3(NE / BN, M / BM), 256, SMEM_GEMM>>>(bu, out);

    scat_add<<<BHC / 8, 256>>>(att);
}

// round 15
// speedup vs baseline: 1.2751x; 1.2751x over previous
#include <cuda_runtime.h>
#include <cuda_bf16.h>
#include <cstdint>

// ---------------- problem constants ----------------
constexpr int NB  = 2;
constexpr int NH  = 8;
constexpr int NC  = 2048;
constexpr int NE  = 1024;
constexpr int ND  = 64;
constexpr int NKP = 8;
constexpr int NP  = 16;
constexpr int BHC = NB * NH * NC;          // 32768
constexpr int HD  = NH * ND;               // 512
constexpr int M   = NB * NC;               // 4096
constexpr int NQKV = 3 * HD;               // 1536

// ---------------- scratch (__device__ globals; no allocation allowed) ----------------
__device__ float g_Q[NB * NH * NC * ND];
__device__ float g_K[NB * NH * NC * ND];
__device__ float g_V[NB * NH * NC * ND];
__device__ int   g_idx[BHC * NP];
__device__ float g_dens[(size_t)BHC * 128];
__device__ float g_part[NB * NH * 16 * 128];       // phase-1 partial sums
__device__ float g_Sinv[NB * NH * 128];
__device__ float g_w[BHC * NP];
__device__ float g_nw[BHC * NP];

// bf16 split operands
__device__ __nv_bfloat16 g_xh[(size_t)M * NE];
__device__ __nv_bfloat16 g_xl[(size_t)M * NE];
__device__ __nv_bfloat16 g_Wqkvh[(size_t)NQKV * NE];   // [n, k] K-major, scale folded
__device__ __nv_bfloat16 g_Wqkvl[(size_t)NQKV * NE];
__device__ __nv_bfloat16 g_Wuh[(size_t)NE * HD];       // [n=1024, k=512]
__device__ __nv_bfloat16 g_Wul[(size_t)NE * HD];
__device__ __nv_bfloat16 g_uh[(size_t)M * HD];
__device__ __nv_bfloat16 g_ul[(size_t)M * HD];

// ---------------- PTX helpers ----------------
__device__ __forceinline__ uint32_t smem_u32(const void* p) {
    uint32_t a;
    asm("{ .reg .u64 t; cvta.to.shared.u64 t, %1; cvt.u32.u64 %0, t; }" : "=r"(a) : "l"(p));
    return a;
}

__device__ __forceinline__ void cp_async16(uint32_t dst, const void* src) {
    asm volatile("cp.async.cg.shared.global [%0], [%1], 16;" :: "r"(dst), "l"(src) : "memory");
}

__device__ __forceinline__ void ldsm_x4(uint32_t* r, uint32_t addr) {
    asm volatile("ldmatrix.sync.aligned.m8n8.x4.shared.b16 {%0,%1,%2,%3}, [%4];"
                 : "=r"(r[0]), "=r"(r[1]), "=r"(r[2]), "=r"(r[3]) : "r"(addr));
}

__device__ __forceinline__ void mma16816(float* c, const uint32_t* a,
                                         uint32_t b0, uint32_t b1) {
    asm volatile(
        "mma.sync.aligned.m16n8k16.row.col.f32.bf16.bf16.f32 "
        "{%0,%1,%2,%3}, {%4,%5,%6,%7}, {%8,%9}, {%0,%1,%2,%3};"
        : "+f"(c[0]), "+f"(c[1]), "+f"(c[2]), "+f"(c[3])
        : "r"(a[0]), "r"(a[1]), "r"(a[2]), "r"(a[3]), "r"(b0), "r"(b1));
}

// ---------------- conversion kernels ----------------
__global__ __launch_bounds__(256) void conv_x(const float* __restrict__ in)
{
    const int i = blockIdx.x * blockDim.x + threadIdx.x;      // pairs
    float2 v = ((const float2*)in)[i];
    __nv_bfloat16 h0 = __float2bfloat16(v.x), h1 = __float2bfloat16(v.y);
    __nv_bfloat162 hv; hv.x = h0; hv.y = h1;
    __nv_bfloat162 lv;
    lv.x = __float2bfloat16(v.x - __bfloat162float(h0));
    lv.y = __float2bfloat16(v.y - __bfloat162float(h1));
    ((__nv_bfloat162*)g_xh)[i] = hv;
    ((__nv_bfloat162*)g_xl)[i] = lv;
}

// fused coalesced transpose of all 4 weight matrices: W[k,n] -> Wt[n,k] hi/lo bf16
__global__ __launch_bounds__(256) void conv_w(const float* __restrict__ Wq,
                                              const float* __restrict__ Wk,
                                              const float* __restrict__ Wv,
                                              const float* __restrict__ Wu)
{
    __shared__ float sm[32][33];
    const int bid = blockIdx.x;
    const int mat = bid >> 9;          // 512 tiles per matrix
    const int t   = bid & 511;

    const float* src;
    __nv_bfloat16 *oh, *ol;
    int cols_in, Kd;
    float scale;
    if (mat == 0)      { src = Wq; oh = g_Wqkvh;                       ol = g_Wqkvl;                       cols_in = 512;  Kd = 1024; scale = 0.125f; }
    else if (mat == 1) { src = Wk; oh = g_Wqkvh + (size_t)HD * NE;     ol = g_Wqkvl + (size_t)HD * NE;     cols_in = 512;  Kd = 1024; scale = 0.125f; }
    else if (mat == 2) { src = Wv; oh = g_Wqkvh + (size_t)2 * HD * NE; ol = g_Wqkvl + (size_t)2 * HD * NE; cols_in = 512;  Kd = 1024; scale = 1.0f;   }
    else               { src = Wu; oh = g_Wuh;                         ol = g_Wul;                         cols_in = 1024; Kd = 512;  scale = 1.0f;   }

    int tn, tk;
    if (mat < 3) { tn = t & 15; tk = t >> 4; }
    else         { tn = t & 31; tk = t >> 5; }
    const int k0 = tk * 32, n0 = tn * 32;

    const int c = threadIdx.x & 31;
    const int r = threadIdx.x >> 5;
#pragma unroll
    for (int rr = 0; rr < 4; rr++) {
        const int row = r + rr * 8;
        sm[row][c] = src[(size_t)(k0 + row) * cols_in + n0 + c];
    }
    __syncthreads();
#pragma unroll
    for (int rr = 0; rr < 4; rr++) {
        const int rp = r + rr * 8;
        const int n = n0 + rp;
        const int k = k0 + c;
        float v = sm[c][rp] * scale;
        __nv_bfloat16 h = __float2bfloat16(v);
        oh[(size_t)n * Kd + k] = h;
        ol[(size_t)n * Kd + k] = __float2bfloat16(v - __bfloat162float(h));
    }
}

// ---------------- shared GEMM geometry ----------------
constexpr int BM = 128, BK = 16;
constexpr int ROWB  = 48;                    // padded row stride (bytes) for 32B of data
constexpr int A_MAT = 128 * ROWB;            // 6144 bytes per 128-row matrix tile

// ======== gemm0: BN=64, 128 threads, 3 CTAs/SM (wave-quantization fix) ========
constexpr int BN0    = 64;
constexpr int B_MAT0 = 64 * ROWB;            // 3072
constexpr int STG0   = 2 * A_MAT + 2 * B_MAT0;   // 18432
constexpr int SMEM_G0 = 4 * STG0;            // 73728
constexpr int G0X    = NQKV / BN0;           // 24
constexpr int G0_TILES = G0X * (M / BM);     // 768

__global__ __launch_bounds__(128, 3)
void gemm0_k()
{
    constexpr int K   = NE;
    constexpr int NCH = K / BK;              // 64

    extern __shared__ char sm[];
    const uint32_t sb = smem_u32(sm);

    const int tid  = threadIdx.x;
    const int wid  = tid >> 5;
    const int lane = tid & 31;
    const int warp_m = wid & 1;        // 0..1 -> 64-row slice
    const int warp_n = wid >> 1;       // 0..1 -> 32-col slice
    const int bx = blockIdx.x % G0X;
    const int by = blockIdx.x / G0X;
    const int row0 = by * BM;
    const int col0 = bx * BN0;

    // cp.async mapping: 768 16B chunks per stage, 6 per thread
    const char* gsrc[6];
    uint32_t    sdst[6];
#pragma unroll
    for (int i = 0; i < 6; i++) {
        const int u = tid + i * 128;
        const int c = u & 1;
        int mat, r;
        if (u < 512) { mat = u >> 8;               r = (u >> 1) & 127; }
        else         { mat = 2 + ((u - 512) >> 7); r = ((u - 512) >> 1) & 63; }
        const __nv_bfloat16* base = (mat == 0) ? g_xh : (mat == 1) ? g_xl
                                  : (mat == 2) ? g_Wqkvh : g_Wqkvl;
        const int rb = (mat < 2) ? row0 : col0;
        gsrc[i] = (const char*)(base + (size_t)(rb + r) * K) + c * 16;
        const uint32_t mb = (mat == 0) ? 0u : (mat == 1) ? (uint32_t)A_MAT
                          : (mat == 2) ? (uint32_t)(2 * A_MAT)
                          : (uint32_t)(2 * A_MAT + B_MAT0);
        sdst[i] = sb + mb + r * ROWB + c * 16;
    }

    float acc[4][4][4];
#pragma unroll
    for (int a = 0; a < 4; a++)
#pragma unroll
        for (int b = 0; b < 4; b++)
#pragma unroll
            for (int d = 0; d < 4; d++) acc[a][b][d] = 0.f;

    const uint32_t a_addr = sb + (warp_m * 64 + (lane & 15)) * ROWB + ((lane >> 4) & 1) * 16;
    const uint32_t b_addr = sb + 2 * A_MAT +
        (warp_n * 32 + (lane & 7) + ((lane & 16) ? 8 : 0)) * ROWB + ((lane & 8) ? 16 : 0);

    // prologue: stages 0..2
#pragma unroll
    for (int s = 0; s < 3; s++) {
#pragma unroll
        for (int i = 0; i < 6; i++)
            cp_async16(sdst[i] + s * STG0, gsrc[i] + (size_t)s * 32);
        asm volatile("cp.async.commit_group;" ::: "memory");
    }

    for (int kb = 0; kb < NCH; kb++) {
        asm volatile("cp.async.wait_group 2;" ::: "memory");
        __syncthreads();

        const uint32_t so = (kb & 3) * STG0;
        uint32_t ah[4][4], al[4][4], bh[2][4], bl[2][4];
#pragma unroll
        for (int mf = 0; mf < 4; mf++) ldsm_x4(ah[mf], a_addr + so + mf * 16 * ROWB);
#pragma unroll
        for (int mf = 0; mf < 4; mf++) ldsm_x4(al[mf], a_addr + so + A_MAT + mf * 16 * ROWB);
#pragma unroll
        for (int gp = 0; gp < 2; gp++) ldsm_x4(bh[gp], b_addr + so + gp * 16 * ROWB);
#pragma unroll
        for (int gp = 0; gp < 2; gp++) ldsm_x4(bl[gp], b_addr + so + B_MAT0 + gp * 16 * ROWB);

#pragma unroll
        for (int term = 0; term < 3; term++) {
#pragma unroll
            for (int mf = 0; mf < 4; mf++)
#pragma unroll
                for (int nf = 0; nf < 4; nf++) {
                    const uint32_t* af = (term == 2) ? al[mf] : ah[mf];
                    const uint32_t b0 = (term == 1) ? bl[nf >> 1][(nf & 1) * 2]
                                                    : bh[nf >> 1][(nf & 1) * 2];
                    const uint32_t b1 = (term == 1) ? bl[nf >> 1][(nf & 1) * 2 + 1]
                                                    : bh[nf >> 1][(nf & 1) * 2 + 1];
                    mma16816(acc[mf][nf], af, b0, b1);
                }
        }

        if (kb + 3 < NCH) {
            const uint32_t sn = ((kb + 3) & 3) * STG0;
#pragma unroll
            for (int i = 0; i < 6; i++)
                cp_async16(sdst[i] + sn, gsrc[i] + (size_t)(kb + 3) * 32);
            asm volatile("cp.async.commit_group;" ::: "memory");
        }
    }

    // epilogue -> g_Q/g_K/g_V (b,h,c,d)
    const int gid = lane >> 2;
    const int tig = lane & 3;
#pragma unroll
    for (int mf = 0; mf < 4; mf++) {
#pragma unroll
        for (int nf = 0; nf < 4; nf++) {
            const int mrow = row0 + warp_m * 64 + mf * 16 + gid;
            const int ncol = col0 + warp_n * 32 + nf * 8 + tig * 2;
            const int mat = ncol >> 9;
            const int hd0 = ncol & 511;
            float* base = (mat == 0) ? g_Q : (mat == 1) ? g_K : g_V;
            const int h = hd0 >> 6, d = hd0 & 63;
#pragma unroll
            for (int half = 0; half < 2; half++) {
                const int m = mrow + half * 8;
                const size_t off =
                    ((size_t)(((m >> 11) * NH + h) * NC + (m & (NC - 1)))) * ND + d;
                *(float2*)(base + off) =
                    make_float2(acc[mf][nf][half * 2], acc[mf][nf][half * 2 + 1]);
            }
        }
    }
}

// ======== gemm1: BN=128, 256 threads (proven R12 config) ========
constexpr int BN1   = 128;
constexpr int STG1  = 4 * A_MAT;             // Ah, Al, Bh, Bl = 24576
constexpr int SMEM_G1 = 4 * STG1;            // 98304

__global__ __launch_bounds__(256, 2)
void gemm1_k(const float* __restrict__ bias, float* __restrict__ outp)
{
    constexpr int K   = HD;
    constexpr int NCH = K / BK;              // 32

    extern __shared__ char sm[];
    const uint32_t sb = smem_u32(sm);

    const int tid  = threadIdx.x;
    const int wid  = tid >> 5;
    const int lane = tid & 31;
    const int warp_m = wid & 1;
    const int warp_n = wid >> 1;
    const int row0 = blockIdx.y * BM;
    const int col0 = blockIdx.x * BN1;

    const char* gsrc[4];
    uint32_t    sdst[4];
#pragma unroll
    for (int i = 0; i < 4; i++) {
        const int u   = tid + i * 256;
        const int mat = u >> 8;
        const int r   = (u >> 1) & 127;
        const int c   = u & 1;
        const __nv_bfloat16* base = (mat == 0) ? g_uh : (mat == 1) ? g_ul
                                  : (mat == 2) ? g_Wuh : g_Wul;
        const int rb = (mat < 2) ? row0 : col0;
        gsrc[i] = (const char*)(base + (size_t)(rb + r) * K) + c * 16;
        sdst[i] = sb + mat * A_MAT + r * ROWB + c * 16;
    }

    float acc[4][4][4];
#pragma unroll
    for (int a = 0; a < 4; a++)
#pragma unroll
        for (int b = 0; b < 4; b++)
#pragma unroll
            for (int d = 0; d < 4; d++) acc[a][b][d] = 0.f;

    const uint32_t a_addr = sb + (warp_m * 64 + (lane & 15)) * ROWB + ((lane >> 4) & 1) * 16;
    const uint32_t b_addr = sb + 2 * A_MAT +
        (warp_n * 32 + (lane & 7) + ((lane & 16) ? 8 : 0)) * ROWB + ((lane & 8) ? 16 : 0);

#pragma unroll
    for (int s = 0; s < 3; s++) {
#pragma unroll
        for (int i = 0; i < 4; i++)
            cp_async16(sdst[i] + s * STG1, gsrc[i] + (size_t)s * 32);
        asm volatile("cp.async.commit_group;" ::: "memory");
    }

    for (int kb = 0; kb < NCH; kb++) {
        asm volatile("cp.async.wait_group 2;" ::: "memory");
        __syncthreads();

        const uint32_t so = (kb & 3) * STG1;
        uint32_t ah[4][4], al[4][4], bh[2][4], bl[2][4];
#pragma unroll
        for (int mf = 0; mf < 4; mf++) ldsm_x4(ah[mf], a_addr + so + mf * 16 * ROWB);
#pragma unroll
        for (int mf = 0; mf < 4; mf++) ldsm_x4(al[mf], a_addr + so + A_MAT + mf * 16 * ROWB);
#pragma unroll
        for (int gp = 0; gp < 2; gp++) ldsm_x4(bh[gp], b_addr + so + gp * 16 * ROWB);
#pragma unroll
        for (int gp = 0; gp < 2; gp++) ldsm_x4(bl[gp], b_addr + so + A_MAT + gp * 16 * ROWB);

#pragma unroll
        for (int term = 0; term < 3; term++) {
#pragma unroll
            for (int mf = 0; mf < 4; mf++)
#pragma unroll
                for (int nf = 0; nf < 4; nf++) {
                    const uint32_t* af = (term == 2) ? al[mf] : ah[mf];
                    const uint32_t b0 = (term == 1) ? bl[nf >> 1][(nf & 1) * 2]
                                                    : bh[nf >> 1][(nf & 1) * 2];
                    const uint32_t b1 = (term == 1) ? bl[nf >> 1][(nf & 1) * 2 + 1]
                                                    : bh[nf >> 1][(nf & 1) * 2 + 1];
                    mma16816(acc[mf][nf], af, b0, b1);
                }
        }

        if (kb + 3 < NCH) {
            const uint32_t sn = ((kb + 3) & 3) * STG1;
#pragma unroll
            for (int i = 0; i < 4; i++)
                cp_async16(sdst[i] + sn, gsrc[i] + (size_t)(kb + 3) * 32);
            asm volatile("cp.async.commit_group;" ::: "memory");
        }
    }

    const int gid = lane >> 2;
    const int tig = lane & 3;
#pragma unroll
    for (int mf = 0; mf < 4; mf++) {
#pragma unroll
        for (int nf = 0; nf < 4; nf++) {
            const int mrow = row0 + warp_m * 64 + mf * 16 + gid;
            const int ncol = col0 + warp_n * 32 + nf * 8 + tig * 2;
            const float2 bb = *(const float2*)(bias + ncol);
#pragma unroll
            for (int half = 0; half < 2; half++) {
                const int m = mrow + half * 8;
                *(float2*)(outp + (size_t)m * NE + ncol) =
                    make_float2(acc[mf][nf][half * 2] + bb.x,
                                acc[mf][nf][half * 2 + 1] + bb.y);
            }
        }
    }
}

// ---------------- idx + per-point densities (warp per (b,h,c), lane-parallel) ----------------
__global__ __launch_bounds__(256)
void dens_k(const float* __restrict__ means, const float* __restrict__ sigmas)
{
    const unsigned FULL = 0xffffffffu;
    const int gw   = (blockIdx.x * blockDim.x + threadIdx.x) >> 5;
    const int lane = threadIdx.x & 31;
    if (gw >= BHC) return;

    float mk = 0.f, sk = 1.f;
    if (lane < NKP) {
        mk = means[(size_t)gw * NKP + lane];
        sk = sigmas[(size_t)gw * NKP + lane];
    }

    const int pl = lane & 15;
    const float mp = __shfl_sync(FULL, mk, pl >> 1);
    int i0 = min(NC - 1, max(0, (int)floorf(mp)));
    const int myidx = (pl & 1) ? min(NC - 1, i0 + 1) : i0;

    const unsigned peers = __match_any_sync(FULL, myidx);
    const int mydup = ((peers & 0xFFFFu & ((1u << pl) - 1u)) != 0) ? 1 : 0;

    if (lane < NP) g_idx[gw * NP + lane] = myidx;

    const int   ip  = __shfl_sync(FULL, myidx, lane >> 1);
    const int   dp_ = __shfl_sync(FULL, mydup, lane >> 1);
    const float fi  = (float)ip;
    const int kb4 = (lane & 1) * 4;
    float dv[4];
#pragma unroll
    for (int u = 0; u < 4; u++) {
        const float mku = __shfl_sync(FULL, mk, kb4 + u);
        const float sku = __shfl_sync(FULL, sk, kb4 + u);
        const float t = (fi - mku) / sku;
        dv[u] = dp_ ? 0.f : __expf(-0.5f * t * t);
    }
    *(float4*)&g_dens[(size_t)gw * 128 + lane * 4] =
        make_float4(dv[0], dv[1], dv[2], dv[3]);
}

// ---------------- reduce densities over c: phase 1 (256 blocks) ----------------
__global__ __launch_bounds__(256)
void sum1_k()
{
    const int bh    = blockIdx.x >> 4;
    const int slice = blockIdx.x & 15;
    const int tid   = threadIdx.x;
    const int pk    = tid & 127;
    const int half  = tid >> 7;
    float acc = 0.f;
    const float* dp = g_dens + ((size_t)bh * NC + slice * 128) * 128 + pk;
    for (int c = half; c < 128; c += 2) acc += dp[(size_t)c * 128];
    __shared__ float sh[256];
    sh[tid] = acc;
    __syncthreads();
    if (tid < 128)
        g_part[blockIdx.x * 128 + tid] = sh[tid] + sh[tid + 128];
}

// ---------------- phase 2: fold 16 partials, invert ----------------
__global__ __launch_bounds__(128)
void sum2_k()
{
    const int bh  = blockIdx.x;
    const int tid = threadIdx.x;
    float acc = 0.f;
#pragma unroll
    for (int s = 0; s < 16; s++)
        acc += g_part[(bh * 16 + s) * 128 + tid];
    g_Sinv[bh * 128 + tid] = 1.0f / (acc + 1e-8f);
}

// ---------------- density-weighted values -> per-point weights ----------------
__global__ __launch_bounds__(256)
void wgt_k(const float* __restrict__ values)
{
    const int gid  = blockIdx.x * blockDim.x + threadIdx.x;
    const int base = gid >> 4;
    const int p    = gid & 15;
    const int bh   = base >> 11;
    const float* vv = values + (size_t)base * NKP;
    const float* dd = g_dens + (size_t)base * 128 + p * 8;
    const float* si = g_Sinv + bh * 128 + p * 8;
    float w = 0.f;
#pragma unroll
    for (int k = 0; k < NKP; k++) w += vv[k] * dd[k] * si[k];
    g_w[gid] = w;
}

// ---------------- attention core (warp per (b,h,c)) ----------------
// epilogue writes the bf16 hi/lo split of 'united' directly (fused conv_u)
__global__ __launch_bounds__(256)
void attn_k()
{
    const unsigned FULL = 0xffffffffu;
    const int gw   = (blockIdx.x * blockDim.x + threadIdx.x) >> 5;
    const int lane = threadIdx.x & 31;
    if (gw >= BHC) return;
    const int bh = gw >> 11;

    const float2* Q2 = (const float2*)g_Q;
    const float2* K2 = (const float2*)g_K + (size_t)bh * NC * 32;
    const float2* V2 = (const float2*)g_V + (size_t)bh * NC * 32;

    const float2 q = Q2[(size_t)gw * 32 + lane];

    int   myidx = 0;
    float myw   = 0.f;
    if (lane < NP) {
        myidx = g_idx[gw * NP + lane];
        myw   = g_w[gw * NP + lane];
    }

    float dot[NP];
#pragma unroll
    for (int p = 0; p < NP; p++) {
        const int ip = __shfl_sync(FULL, myidx, p);
        const float2 kv = K2[(size_t)ip * 32 + lane];
        float pa = q.x * kv.x + q.y * kv.y;
#pragma unroll
        for (int o = 16; o > 0; o >>= 1) pa += __shfl_xor_sync(FULL, pa, o);
        dot[p] = pa;
    }

    float lg[NP], mx = -3.0e38f;
#pragma unroll
    for (int p = 0; p < NP; p++) {
        const float wp = __shfl_sync(FULL, myw, p);
        lg[p] = wp * dot[p];
        mx = fmaxf(mx, lg[p]);
    }
    float ssum = 0.f;
#pragma unroll
    for (int p = 0; p < NP; p++) {
        lg[p] = expf(lg[p] - mx);
        ssum += lg[p];
    }
    const float inv = 1.0f / ssum;

    float2 acc = make_float2(0.f, 0.f);
#pragma unroll
    for (int p = 0; p < NP; p++) {
        const float nw = lg[p] * inv;
        lg[p] = nw;
        const int ip = __shfl_sync(FULL, myidx, p);
        const float2 vv = V2[(size_t)ip * 32 + lane];
        acc.x = fmaf(nw, vv.x, acc.x);
        acc.y = fmaf(nw, vv.y, acc.y);
    }

    const int b = gw >> 14;
    const int h = (gw >> 11) & (NH - 1);
    const int c = gw & (NC - 1);
    __nv_bfloat162 hv, lv;
    hv.x = __float2bfloat16(acc.x);
    hv.y = __float2bfloat16(acc.y);
    lv.x = __float2bfloat16(acc.x - __bfloat162float(hv.x));
    lv.y = __float2bfloat16(acc.y - __bfloat162float(hv.y));
    const size_t uoff = (size_t)(b * NC + c) * (HD / 2) + h * (ND / 2) + lane;
    ((__nv_bfloat162*)g_uh)[uoff] = hv;
    ((__nv_bfloat162*)g_ul)[uoff] = lv;

    if (lane < NP) g_nw[gw * NP + lane] = lg[lane];
}

// ---------------- full-row attentions writer (block per row, smem-staged) ----------------
__global__ __launch_bounds__(256)
void scat_k(float* __restrict__ att)
{
    const unsigned FULL = 0xffffffffu;
    __shared__ float row[NC];                // 8 KB
    const int base = blockIdx.x;             // (b*H + h)*C + c
    const int tid  = threadIdx.x;

    float4* r4 = (float4*)row;
    const float4 z = make_float4(0.f, 0.f, 0.f, 0.f);
    r4[tid] = z;
    r4[tid + 256] = z;
    __syncthreads();

    if (tid < 32) {
        int   myidx = -1 - tid;              // unique sentinel for lanes >= NP
        float mynw  = 0.f;
        if (tid < NP) {
            myidx = g_idx[base * NP + tid];
            mynw  = g_nw[base * NP + tid];
        }
        float s = 0.f;
        int leader = tid;
#pragma unroll
        for (int q = 0; q < NP; q++) {
            const int   iq = __shfl_sync(FULL, myidx, q);
            const float nq = __shfl_sync(FULL, mynw, q);
            if (iq == myidx) {
                s += nq;
                if (q < leader) leader = q;
            }
        }
        if (tid < NP && tid == leader) row[myidx] = s;
    }
    __syncthreads();

    float4* d4 = (float4*)(att + (size_t)base * NC);
    d4[tid] = r4[tid];
    d4[tid + 256] = r4[tid + 256];
}

// ---------------- launch ----------------
extern "C" void kernel_launch(void* const* d_in, const int* in_sizes, int n_in,
                              void* d_out, int out_size)
{
    const float* x      = (const float*)d_in[0];
    // d_in[1] = attention_mask (unused)
    const float* means  = (const float*)d_in[2];
    const float* sigmas = (const float*)d_in[3];
    const float* values = (const float*)d_in[4];
    const float* Wk     = (const float*)d_in[5];
    const float* Wq     = (const float*)d_in[6];
    const float* Wv     = (const float*)d_in[7];
    const float* Wu     = (const float*)d_in[8];
    const float* bu     = (const float*)d_in[9];

    float* out = (float*)d_out;
    float* att = out + (size_t)NB * NC * NE;

    cudaFuncSetAttribute(gemm0_k, cudaFuncAttributeMaxDynamicSharedMemorySize, SMEM_G0);
    cudaFuncSetAttribute(gemm1_k, cudaFuncAttributeMaxDynamicSharedMemorySize, SMEM_G1);

    // operand conversion (coalesced)
    conv_x<<<(M * NE / 2) / 256, 256>>>(x);
    conv_w<<<2048, 256>>>(Wq, Wk, Wv, Wu);
    dens_k<<<BHC / 8, 256>>>(means, sigmas);   // 3rd: independent of convs

    // 4th launch -> profiled
    gemm0_k<<<G0_TILES, 128, SMEM_G0>>>();

    sum1_k<<<NB * NH * 16, 256>>>();
    sum2_k<<<NB * NH, 128>>>();
    wgt_k<<<BHC * NP / 256, 256>>>(values);
    attn_k<<<BHC / 8, 256>>>();

    gemm1_k<<<dim3(NE / BN1, M / BM), 256, SMEM_G1>>>(bu, out);

    scat_k<<<BHC, 256>>>(att);
}

// round 16
// speedup vs baseline: 1.4185x; 1.1125x over previous
#include <cuda_runtime.h>
#include <cuda_bf16.h>
#include <cstdint>

// ---------------- problem constants ----------------
constexpr int NB  = 2;
constexpr int NH  = 8;
constexpr int NC  = 2048;
constexpr int NE  = 1024;
constexpr int ND  = 64;
constexpr int NKP = 8;
constexpr int NP  = 16;
constexpr int BHC = NB * NH * NC;          // 32768
constexpr int HD  = NH * ND;               // 512
constexpr int M   = NB * NC;               // 4096
constexpr int NQKV = 3 * HD;               // 1536

// ---------------- scratch (__device__ globals; no allocation allowed) ----------------
__device__ float g_Q[NB * NH * NC * ND];
__device__ float g_K[NB * NH * NC * ND];
__device__ float g_V[NB * NH * NC * ND];
__device__ int   g_idx[BHC * NP];
__device__ float g_dens[(size_t)BHC * 128];
__device__ float g_part[NB * NH * 16 * 128];       // phase-1 partial sums
__device__ float g_Sinv[NB * NH * 128];
__device__ float g_w[BHC * NP];
__device__ float g_nw[BHC * NP];

// bf16 split operands
__device__ __nv_bfloat16 g_xh[(size_t)M * NE];
__device__ __nv_bfloat16 g_xl[(size_t)M * NE];
__device__ __nv_bfloat16 g_Wqkvh[(size_t)NQKV * NE];   // [n, k] K-major, scale folded
__device__ __nv_bfloat16 g_Wqkvl[(size_t)NQKV * NE];
__device__ __nv_bfloat16 g_Wuh[(size_t)NE * HD];       // [n=1024, k=512]
__device__ __nv_bfloat16 g_Wul[(size_t)NE * HD];
__device__ __nv_bfloat16 g_uh[(size_t)M * HD];
__device__ __nv_bfloat16 g_ul[(size_t)M * HD];

// ---------------- PTX helpers ----------------
__device__ __forceinline__ uint32_t smem_u32(const void* p) {
    uint32_t a;
    asm("{ .reg .u64 t; cvta.to.shared.u64 t, %1; cvt.u32.u64 %0, t; }" : "=r"(a) : "l"(p));
    return a;
}

__device__ __forceinline__ void cp_async16(uint32_t dst, const void* src) {
    asm volatile("cp.async.cg.shared.global [%0], [%1], 16;" :: "r"(dst), "l"(src) : "memory");
}

__device__ __forceinline__ void ldsm_x4(uint32_t* r, uint32_t addr) {
    asm volatile("ldmatrix.sync.aligned.m8n8.x4.shared.b16 {%0,%1,%2,%3}, [%4];"
                 : "=r"(r[0]), "=r"(r[1]), "=r"(r[2]), "=r"(r[3]) : "r"(addr));
}

__device__ __forceinline__ void mma16816(float* c, const uint32_t* a,
                                         uint32_t b0, uint32_t b1) {
    asm volatile(
        "mma.sync.aligned.m16n8k16.row.col.f32.bf16.bf16.f32 "
        "{%0,%1,%2,%3}, {%4,%5,%6,%7}, {%8,%9}, {%0,%1,%2,%3};"
        : "+f"(c[0]), "+f"(c[1]), "+f"(c[2]), "+f"(c[3])
        : "r"(a[0]), "r"(a[1]), "r"(a[2]), "r"(a[3]), "r"(b0), "r"(b1));
}

// ---------------- conversion kernels ----------------
__global__ __launch_bounds__(256) void conv_x(const float* __restrict__ in)
{
    const int i = blockIdx.x * blockDim.x + threadIdx.x;      // pairs
    float2 v = ((const float2*)in)[i];
    __nv_bfloat16 h0 = __float2bfloat16(v.x), h1 = __float2bfloat16(v.y);
    __nv_bfloat162 hv; hv.x = h0; hv.y = h1;
    __nv_bfloat162 lv;
    lv.x = __float2bfloat16(v.x - __bfloat162float(h0));
    lv.y = __float2bfloat16(v.y - __bfloat162float(h1));
    ((__nv_bfloat162*)g_xh)[i] = hv;
    ((__nv_bfloat162*)g_xl)[i] = lv;
}

// fused coalesced transpose of all 4 weight matrices: W[k,n] -> Wt[n,k] hi/lo bf16
__global__ __launch_bounds__(256) void conv_w(const float* __restrict__ Wq,
                                              const float* __restrict__ Wk,
                                              const float* __restrict__ Wv,
                                              const float* __restrict__ Wu)
{
    __shared__ float sm[32][33];
    const int bid = blockIdx.x;
    const int mat = bid >> 9;          // 512 tiles per matrix
    const int t   = bid & 511;

    const float* src;
    __nv_bfloat16 *oh, *ol;
    int cols_in, Kd;
    float scale;
    if (mat == 0)      { src = Wq; oh = g_Wqkvh;                       ol = g_Wqkvl;                       cols_in = 512;  Kd = 1024; scale = 0.125f; }
    else if (mat == 1) { src = Wk; oh = g_Wqkvh + (size_t)HD * NE;     ol = g_Wqkvl + (size_t)HD * NE;     cols_in = 512;  Kd = 1024; scale = 0.125f; }
    else if (mat == 2) { src = Wv; oh = g_Wqkvh + (size_t)2 * HD * NE; ol = g_Wqkvl + (size_t)2 * HD * NE; cols_in = 512;  Kd = 1024; scale = 1.0f;   }
    else               { src = Wu; oh = g_Wuh;                         ol = g_Wul;                         cols_in = 1024; Kd = 512;  scale = 1.0f;   }

    int tn, tk;
    if (mat < 3) { tn = t & 15; tk = t >> 4; }
    else         { tn = t & 31; tk = t >> 5; }
    const int k0 = tk * 32, n0 = tn * 32;

    const int c = threadIdx.x & 31;
    const int r = threadIdx.x >> 5;
#pragma unroll
    for (int rr = 0; rr < 4; rr++) {
        const int row = r + rr * 8;
        sm[row][c] = src[(size_t)(k0 + row) * cols_in + n0 + c];
    }
    __syncthreads();
#pragma unroll
    for (int rr = 0; rr < 4; rr++) {
        const int rp = r + rr * 8;
        const int n = n0 + rp;
        const int k = k0 + c;
        float v = sm[c][rp] * scale;
        __nv_bfloat16 h = __float2bfloat16(v);
        oh[(size_t)n * Kd + k] = h;
        ol[(size_t)n * Kd + k] = __float2bfloat16(v - __bfloat162float(h));
    }
}

// ---------------- HMMA bf16-split GEMM (R12-proven: BN=128, 256 thr, 4 stages, wait 2) ----------------
// MODE 0: C = x @ [Wq*s | Wk*s | Wv]  (K=1024, N=1536) -> g_Q/g_K/g_V (b,h,c,d)
// MODE 1: C = united @ Wu + bu        (K=512,  N=1024) -> outp row-major
constexpr int BM = 128, BN = 128, BK = 16;
constexpr int ROWB  = 48;                    // padded row stride (bytes) for 32B of data
constexpr int MAT_B = 128 * ROWB;            // 6144 bytes per matrix tile
constexpr int STG_B = 4 * MAT_B;             // Ah, Al, Bh, Bl  = 24576
constexpr int NSTG  = 4;
constexpr int SMEM_GEMM = NSTG * STG_B;      // 98304

template <int MODE>
__global__ __launch_bounds__(256, 2)
void gemm_mma(const float* __restrict__ bias, float* __restrict__ outp)
{
    constexpr int K   = (MODE == 0) ? NE : HD;
    constexpr int NCH = K / BK;

    extern __shared__ char sm[];
    const uint32_t sb = smem_u32(sm);

    const int tid  = threadIdx.x;
    const int wid  = tid >> 5;
    const int lane = tid & 31;
    const int warp_m = wid & 1;        // 0..1 -> 64-row slice
    const int warp_n = wid >> 1;       // 0..3 -> 32-col slice
    const int row0 = blockIdx.y * BM;
    const int col0 = blockIdx.x * BN;

    const __nv_bfloat16* __restrict__ Ah = (MODE == 0) ? g_xh : g_uh;
    const __nv_bfloat16* __restrict__ Al = (MODE == 0) ? g_xl : g_ul;
    const __nv_bfloat16* __restrict__ Bh = (MODE == 0) ? g_Wqkvh : g_Wuh;
    const __nv_bfloat16* __restrict__ Bl = (MODE == 0) ? g_Wqkvl : g_Wul;

    // per-thread cp.async mapping: 1024 16B chunks (4 mats x 128 rows x 2)
    const char* gsrc[4];
    uint32_t    sdst[4];
#pragma unroll
    for (int i = 0; i < 4; i++) {
        const int u   = tid + i * 256;
        const int mat = u >> 8;
        const int r   = (u >> 1) & 127;
        const int c   = u & 1;
        const __nv_bfloat16* base = (mat == 0) ? Ah : (mat == 1) ? Al
                                  : (mat == 2) ? Bh : Bl;
        const int rb = (mat < 2) ? row0 : col0;
        gsrc[i] = (const char*)(base + (size_t)(rb + r) * K) + c * 16;
        sdst[i] = sb + mat * MAT_B + r * ROWB + c * 16;
    }

    float acc[4][4][4];
#pragma unroll
    for (int a = 0; a < 4; a++)
#pragma unroll
        for (int b = 0; b < 4; b++)
#pragma unroll
            for (int d = 0; d < 4; d++) acc[a][b][d] = 0.f;

    // ldmatrix base addresses (within stage 0)
    const uint32_t a_addr = sb + (warp_m * 64 + (lane & 15)) * ROWB + ((lane >> 4) & 1) * 16;
    const uint32_t b_addr = sb + 2 * MAT_B +
        (warp_n * 32 + (lane & 7) + ((lane & 16) ? 8 : 0)) * ROWB + ((lane & 8) ? 16 : 0);

    // prologue: stages 0..2
#pragma unroll
    for (int s = 0; s < 3; s++) {
#pragma unroll
        for (int i = 0; i < 4; i++)
            cp_async16(sdst[i] + s * STG_B, gsrc[i] + (size_t)s * 32);
        asm volatile("cp.async.commit_group;" ::: "memory");
    }

    for (int kb = 0; kb < NCH; kb++) {
        asm volatile("cp.async.wait_group 2;" ::: "memory");
        __syncthreads();

        const uint32_t so = (kb & (NSTG - 1)) * STG_B;
        uint32_t ah[4][4], al[4][4], bh[2][4], bl[2][4];
#pragma unroll
        for (int mf = 0; mf < 4; mf++) ldsm_x4(ah[mf], a_addr + so + mf * 16 * ROWB);
#pragma unroll
        for (int mf = 0; mf < 4; mf++) ldsm_x4(al[mf], a_addr + so + MAT_B + mf * 16 * ROWB);
#pragma unroll
        for (int gp = 0; gp < 2; gp++) ldsm_x4(bh[gp], b_addr + so + gp * 16 * ROWB);
#pragma unroll
        for (int gp = 0; gp < 2; gp++) ldsm_x4(bl[gp], b_addr + so + MAT_B + gp * 16 * ROWB);

        // term-outer: 16 independent accumulator chains per term
#pragma unroll
        for (int term = 0; term < 3; term++) {
#pragma unroll
            for (int mf = 0; mf < 4; mf++)
#pragma unroll
                for (int nf = 0; nf < 4; nf++) {
                    const uint32_t* af = (term == 2) ? al[mf] : ah[mf];
                    const uint32_t b0 = (term == 1) ? bl[nf >> 1][(nf & 1) * 2]
                                                    : bh[nf >> 1][(nf & 1) * 2];
                    const uint32_t b1 = (term == 1) ? bl[nf >> 1][(nf & 1) * 2 + 1]
                                                    : bh[nf >> 1][(nf & 1) * 2 + 1];
                    mma16816(acc[mf][nf], af, b0, b1);
                }
        }

        if (kb + 3 < NCH) {
            const uint32_t sn = ((kb + 3) & (NSTG - 1)) * STG_B;
#pragma unroll
            for (int i = 0; i < 4; i++)
                cp_async16(sdst[i] + sn, gsrc[i] + (size_t)(kb + 3) * 32);
            asm volatile("cp.async.commit_group;" ::: "memory");
        }
    }

    // epilogue
    const int gid = lane >> 2;
    const int tig = lane & 3;
#pragma unroll
    for (int mf = 0; mf < 4; mf++) {
#pragma unroll
        for (int nf = 0; nf < 4; nf++) {
            const int mrow = row0 + warp_m * 64 + mf * 16 + gid;
            const int ncol = col0 + warp_n * 32 + nf * 8 + tig * 2;
            if (MODE == 0) {
                const int mat = ncol >> 9;
                const int hd0 = ncol & 511;
                float* base = (mat == 0) ? g_Q : (mat == 1) ? g_K : g_V;
                const int h = hd0 >> 6, d = hd0 & 63;
#pragma unroll
                for (int half = 0; half < 2; half++) {
                    const int m = mrow + half * 8;
                    const size_t off =
                        ((size_t)(((m >> 11) * NH + h) * NC + (m & (NC - 1)))) * ND + d;
                    *(float2*)(base + off) =
                        make_float2(acc[mf][nf][half * 2], acc[mf][nf][half * 2 + 1]);
                }
            } else {
                const float2 bb = *(const float2*)(bias + ncol);
#pragma unroll
                for (int half = 0; half < 2; half++) {
                    const int m = mrow + half * 8;
                    *(float2*)(outp + (size_t)m * NE + ncol) =
                        make_float2(acc[mf][nf][half * 2] + bb.x,
                                    acc[mf][nf][half * 2 + 1] + bb.y);
                }
            }
        }
    }
}

// ---------------- idx + per-point densities (warp per (b,h,c), lane-parallel) ----------------
__global__ __launch_bounds__(256)
void dens_k(const float* __restrict__ means, const float* __restrict__ sigmas)
{
    const unsigned FULL = 0xffffffffu;
    const int gw   = (blockIdx.x * blockDim.x + threadIdx.x) >> 5;
    const int lane = threadIdx.x & 31;
    if (gw >= BHC) return;

    float mk = 0.f, sk = 1.f;
    if (lane < NKP) {
        mk = means[(size_t)gw * NKP + lane];
        sk = sigmas[(size_t)gw * NKP + lane];
    }

    const int pl = lane & 15;
    const float mp = __shfl_sync(FULL, mk, pl >> 1);
    int i0 = min(NC - 1, max(0, (int)floorf(mp)));
    const int myidx = (pl & 1) ? min(NC - 1, i0 + 1) : i0;

    const unsigned peers = __match_any_sync(FULL, myidx);
    const int mydup = ((peers & 0xFFFFu & ((1u << pl) - 1u)) != 0) ? 1 : 0;

    if (lane < NP) g_idx[gw * NP + lane] = myidx;

    const int   ip  = __shfl_sync(FULL, myidx, lane >> 1);
    const int   dp_ = __shfl_sync(FULL, mydup, lane >> 1);
    const float fi  = (float)ip;
    const int kb4 = (lane & 1) * 4;
    float dv[4];
#pragma unroll
    for (int u = 0; u < 4; u++) {
        const float mku = __shfl_sync(FULL, mk, kb4 + u);
        const float sku = __shfl_sync(FULL, sk, kb4 + u);
        const float t = (fi - mku) / sku;
        dv[u] = dp_ ? 0.f : __expf(-0.5f * t * t);
    }
    *(float4*)&g_dens[(size_t)gw * 128 + lane * 4] =
        make_float4(dv[0], dv[1], dv[2], dv[3]);
}

// ---------------- reduce densities over c: phase 1 (256 blocks) ----------------
__global__ __launch_bounds__(256)
void sum1_k()
{
    const int bh    = blockIdx.x >> 4;
    const int slice = blockIdx.x & 15;
    const int tid   = threadIdx.x;
    const int pk    = tid & 127;
    const int half  = tid >> 7;
    float acc = 0.f;
    const float* dp = g_dens + ((size_t)bh * NC + slice * 128) * 128 + pk;
    for (int c = half; c < 128; c += 2) acc += dp[(size_t)c * 128];
    __shared__ float sh[256];
    sh[tid] = acc;
    __syncthreads();
    if (tid < 128)
        g_part[blockIdx.x * 128 + tid] = sh[tid] + sh[tid + 128];
}

// ---------------- phase 2: fold 16 partials, invert ----------------
__global__ __launch_bounds__(128)
void sum2_k()
{
    const int bh  = blockIdx.x;
    const int tid = threadIdx.x;
    float acc = 0.f;
#pragma unroll
    for (int s = 0; s < 16; s++)
        acc += g_part[(bh * 16 + s) * 128 + tid];
    g_Sinv[bh * 128 + tid] = 1.0f / (acc + 1e-8f);
}

// ---------------- density-weighted values -> per-point weights ----------------
__global__ __launch_bounds__(256)
void wgt_k(const float* __restrict__ values)
{
    const int gid  = blockIdx.x * blockDim.x + threadIdx.x;
    const int base = gid >> 4;
    const int p    = gid & 15;
    const int bh   = base >> 11;
    const float* vv = values + (size_t)base * NKP;
    const float* dd = g_dens + (size_t)base * 128 + p * 8;
    const float* si = g_Sinv + bh * 128 + p * 8;
    float w = 0.f;
#pragma unroll
    for (int k = 0; k < NKP; k++) w += vv[k] * dd[k] * si[k];
    g_w[gid] = w;
}

// ---------------- attention core (warp per (b,h,c)) ----------------
// epilogue writes the bf16 hi/lo split of 'united' directly (fused conv_u)
__global__ __launch_bounds__(256)
void attn_k()
{
    const unsigned FULL = 0xffffffffu;
    const int gw   = (blockIdx.x * blockDim.x + threadIdx.x) >> 5;
    const int lane = threadIdx.x & 31;
    if (gw >= BHC) return;
    const int bh = gw >> 11;

    const float2* Q2 = (const float2*)g_Q;
    const float2* K2 = (const float2*)g_K + (size_t)bh * NC * 32;
    const float2* V2 = (const float2*)g_V + (size_t)bh * NC * 32;

    const float2 q = Q2[(size_t)gw * 32 + lane];

    int   myidx = 0;
    float myw   = 0.f;
    if (lane < NP) {
        myidx = g_idx[gw * NP + lane];
        myw   = g_w[gw * NP + lane];
    }

    float dot[NP];
#pragma unroll
    for (int p = 0; p < NP; p++) {
        const int ip = __shfl_sync(FULL, myidx, p);
        const float2 kv = K2[(size_t)ip * 32 + lane];
        float pa = q.x * kv.x + q.y * kv.y;
#pragma unroll
        for (int o = 16; o > 0; o >>= 1) pa += __shfl_xor_sync(FULL, pa, o);
        dot[p] = pa;
    }

    float lg[NP], mx = -3.0e38f;
#pragma unroll
    for (int p = 0; p < NP; p++) {
        const float wp = __shfl_sync(FULL, myw, p);
        lg[p] = wp * dot[p];
        mx = fmaxf(mx, lg[p]);
    }
    float ssum = 0.f;
#pragma unroll
    for (int p = 0; p < NP; p++) {
        lg[p] = expf(lg[p] - mx);
        ssum += lg[p];
    }
    const float inv = 1.0f / ssum;

    float2 acc = make_float2(0.f, 0.f);
#pragma unroll
    for (int p = 0; p < NP; p++) {
        const float nw = lg[p] * inv;
        lg[p] = nw;
        const int ip = __shfl_sync(FULL, myidx, p);
        const float2 vv = V2[(size_t)ip * 32 + lane];
        acc.x = fmaf(nw, vv.x, acc.x);
        acc.y = fmaf(nw, vv.y, acc.y);
    }

    const int b = gw >> 14;
    const int h = (gw >> 11) & (NH - 1);
    const int c = gw & (NC - 1);
    __nv_bfloat162 hv, lv;
    hv.x = __float2bfloat16(acc.x);
    hv.y = __float2bfloat16(acc.y);
    lv.x = __float2bfloat16(acc.x - __bfloat162float(hv.x));
    lv.y = __float2bfloat16(acc.y - __bfloat162float(hv.y));
    const size_t uoff = (size_t)(b * NC + c) * (HD / 2) + h * (ND / 2) + lane;
    ((__nv_bfloat162*)g_uh)[uoff] = hv;
    ((__nv_bfloat162*)g_ul)[uoff] = lv;

    if (lane < NP) g_nw[gw * NP + lane] = lg[lane];
}

// ---------------- full-row attentions writer (block per row, smem-staged) ----------------
__global__ __launch_bounds__(256)
void scat_k(float* __restrict__ att)
{
    const unsigned FULL = 0xffffffffu;
    __shared__ float row[NC];                // 8 KB
    const int base = blockIdx.x;             // (b*H + h)*C + c
    const int tid  = threadIdx.x;

    float4* r4 = (float4*)row;
    const float4 z = make_float4(0.f, 0.f, 0.f, 0.f);
    r4[tid] = z;
    r4[tid + 256] = z;
    __syncthreads();

    if (tid < 32) {
        int   myidx = -1 - tid;              // unique sentinel for lanes >= NP
        float mynw  = 0.f;
        if (tid < NP) {
            myidx = g_idx[base * NP + tid];
            mynw  = g_nw[base * NP + tid];
        }
        float s = 0.f;
        int leader = tid;
#pragma unroll
        for (int q = 0; q < NP; q++) {
            const int   iq = __shfl_sync(FULL, myidx, q);
            const float nq = __shfl_sync(FULL, mynw, q);
            if (iq == myidx) {
                s += nq;
                if (q < leader) leader = q;
            }
        }
        if (tid < NP && tid == leader) row[myidx] = s;
    }
    __syncthreads();

    float4* d4 = (float4*)(att + (size_t)base * NC);
    d4[tid] = r4[tid];
    d4[tid + 256] = r4[tid + 256];
}

// ---------------- launch ----------------
extern "C" void kernel_launch(void* const* d_in, const int* in_sizes, int n_in,
                              void* d_out, int out_size)
{
    const float* x      = (const float*)d_in[0];
    // d_in[1] = attention_mask (unused)
    const float* means  = (const float*)d_in[2];
    const float* sigmas = (const float*)d_in[3];
    const float* values = (const float*)d_in[4];
    const float* Wk     = (const float*)d_in[5];
    const float* Wq     = (const float*)d_in[6];
    const float* Wv     = (const float*)d_in[7];
    const float* Wu     = (const float*)d_in[8];
    const float* bu     = (const float*)d_in[9];

    float* out = (float*)d_out;
    float* att = out + (size_t)NB * NC * NE;

    cudaFuncSetAttribute(gemm_mma<0>, cudaFuncAttributeMaxDynamicSharedMemorySize, SMEM_GEMM);
    cudaFuncSetAttribute(gemm_mma<1>, cudaFuncAttributeMaxDynamicSharedMemorySize, SMEM_GEMM);

    // operand conversion (coalesced)
    conv_x<<<(M * NE / 2) / 256, 256>>>(x);
    conv_w<<<2048, 256>>>(Wq, Wk, Wv, Wu);
    dens_k<<<BHC / 8, 256>>>(means, sigmas);   // 3rd: independent of convs

    // 4th launch -> profiled
    gemm_mma<0><<<dim3(NQKV / BN, M / BM), 256, SMEM_GEMM>>>(nullptr, nullptr);

    sum1_k<<<NB * NH * 16, 256>>>();
    sum2_k<<<NB * NH, 128>>>();
    wgt_k<<<BHC * NP / 256, 256>>>(values);
    attn_k<<<BHC / 8, 256>>>();

    gemm_mma<1><<<dim3(NE / BN, M / BM), 256, SMEM_GEMM>>>(bu, out);

    scat_k<<<BHC, 256>>>(att);
}